// round 1
// baseline (speedup 1.0000x reference)
#include <cuda_runtime.h>

// CapsuleConv collapsed to: GEMM (rows=(b,w,a), K=(k,n,x)=384, cols=(m,d)=128) + fused LayerNorm.
//
// Dims (fixed):
#define BB   16
#define NIN  32
#define LL   2048
#define DD   16
#define MM   32
#define KW   3
#define WOUT 2046
#define KKDIM 384   // contraction (k,n,x)
#define NNDIM 128   // output cols (m*4+d)

#define TILE_W 16   // w per CTA
#define ROWS   64   // TILE_W * 4 (a)
#define BK     32   // K-chunk

// Rearranged, pre-scaled weight: Wc[(k*32+n)*4+x][m*4+d] = w[k][n][x][d][m] / 32
__device__ float g_Wc[KKDIM * NNDIM];

__global__ void prep_weight_kernel(const float* __restrict__ w) {
    int idx = blockIdx.x * blockDim.x + threadIdx.x;
    if (idx >= KKDIM * NNDIM) return;
    int kk = idx / NNDIM;     // (k*32+n)*4+x
    int c  = idx % NNDIM;     // m*4+d
    int x_ = kk & 3;
    int kn = kk >> 2;
    int n  = kn & 31;
    int k  = kn >> 5;
    int m  = c >> 2;
    int d  = c & 3;
    // w layout [KW][NIN][4][4][MM]
    float val = w[(((k * NIN + n) * 4 + x_) * 4 + d) * MM + m];
    g_Wc[idx] = val * (1.0f / 32.0f);
}

__global__ __launch_bounds__(256, 3)
void capsule_gemm_ln_kernel(const float* __restrict__ x,
                            const float* __restrict__ gamma,
                            const float* __restrict__ beta,
                            float* __restrict__ out) {
    // smem: during mainloop A_s[BK][ROWS] (2048 f) + B_s[BK][NNDIM] (4096 f) = 24KB
    //       during epilogue reused as S[64][128] = 32KB
    __shared__ float smem[8192];
    float* A_s = smem;                // [32][64], transposed A tile
    float* B_s = smem + BK * ROWS;    // [32][128]

    const int tid = threadIdx.x;
    const int tx  = tid & 31;         // col group: cols tx*4 .. tx*4+3
    const int ty  = tid >> 5;         // row group: rows ty*8 .. ty*8+7

    const int wt = blockIdx.x;        // 0..127
    const int b  = blockIdx.y;        // 0..15
    const int w0 = wt * TILE_W;

    const float* xb = x + (size_t)b * NIN * LL * DD;

    float acc[8][4];
#pragma unroll
    for (int i = 0; i < 8; i++)
#pragma unroll
        for (int j = 0; j < 4; j++) acc[i][j] = 0.0f;

    // 12 K-chunks of 32: chunk t covers k = t/4, n in [(t&3)*8, +8), x in 0..3
    for (int t = 0; t < 12; ++t) {
        const int k  = t >> 2;
        const int n0 = (t & 3) * 8;
        const int kk0 = t * BK;

        __syncthreads();
        // Load A tile: 2048 floats as 512 float4, 2 per thread.
        // float4 i: n_local = i>>6, rem = i&63 (= row = w_local*4 + a)
#pragma unroll
        for (int j = 0; j < 2; ++j) {
            int i   = tid + 256 * j;
            int nl  = i >> 6;
            int rem = i & 63;
            int wl  = rem >> 2;
            int a   = rem & 3;
            int l   = w0 + wl + k;
            if (l > LL - 1) l = LL - 1;  // only rows with w>=WOUT hit this; never stored
            const float4 v = *reinterpret_cast<const float4*>(
                xb + ((size_t)(n0 + nl) * LL + l) * DD + a * 4);
            A_s[(nl * 4 + 0) * ROWS + rem] = v.x;
            A_s[(nl * 4 + 1) * ROWS + rem] = v.y;
            A_s[(nl * 4 + 2) * ROWS + rem] = v.z;
            A_s[(nl * 4 + 3) * ROWS + rem] = v.w;
        }
        // Load B tile: 4096 floats as 1024 float4, 4 per thread (coalesced).
#pragma unroll
        for (int j = 0; j < 4; ++j) {
            int i = tid + 256 * j;
            *reinterpret_cast<float4*>(B_s + i * 4) =
                *reinterpret_cast<const float4*>(g_Wc + kk0 * NNDIM + i * 4);
        }
        __syncthreads();

#pragma unroll
        for (int kk = 0; kk < BK; ++kk) {
            const float4 a0 = *reinterpret_cast<const float4*>(A_s + kk * ROWS + ty * 8);
            const float4 a1 = *reinterpret_cast<const float4*>(A_s + kk * ROWS + ty * 8 + 4);
            const float4 bv = *reinterpret_cast<const float4*>(B_s + kk * NNDIM + tx * 4);
            const float av[8] = {a0.x, a0.y, a0.z, a0.w, a1.x, a1.y, a1.z, a1.w};
            const float bw[4] = {bv.x, bv.y, bv.z, bv.w};
#pragma unroll
            for (int i = 0; i < 8; i++)
#pragma unroll
                for (int j = 0; j < 4; j++)
                    acc[i][j] = fmaf(av[i], bw[j], acc[i][j]);
        }
    }

    // ---- Epilogue: stage tile in smem, fused LayerNorm over (a,d)=16 ----
    __syncthreads();
    float* S = smem;  // [64][128]
#pragma unroll
    for (int i = 0; i < 8; i++) {
        float4 v = make_float4(acc[i][0], acc[i][1], acc[i][2], acc[i][3]);
        *reinterpret_cast<float4*>(S + (ty * 8 + i) * NNDIM + tx * 4) = v;
    }
    __syncthreads();

    // 512 LN groups per tile: (bw_local in 0..15) x (m in 0..31); 2 per thread.
#pragma unroll
    for (int g = 0; g < 2; ++g) {
        const int G   = tid + g * 256;
        const int bwl = G >> 5;
        const int m   = G & 31;
        const int w   = w0 + bwl;
        if (w >= WOUT) continue;

        float vals[16];
#pragma unroll
        for (int a = 0; a < 4; a++) {
            const float4 v = *reinterpret_cast<const float4*>(
                S + (bwl * 4 + a) * NNDIM + m * 4);
            vals[a * 4 + 0] = v.x;
            vals[a * 4 + 1] = v.y;
            vals[a * 4 + 2] = v.z;
            vals[a * 4 + 3] = v.w;
        }
        float mu = 0.0f;
#pragma unroll
        for (int i = 0; i < 16; i++) mu += vals[i];
        mu *= (1.0f / 16.0f);
        float var = 0.0f;
#pragma unroll
        for (int i = 0; i < 16; i++) {
            float dv = vals[i] - mu;
            var = fmaf(dv, dv, var);
        }
        var *= (1.0f / 16.0f);
        const float inv = rsqrtf(var + 1e-5f);

        const size_t base = (((size_t)b * MM + m) * WOUT + w) * 16;
        float4 o;
#pragma unroll
        for (int q = 0; q < 4; q++) {
            o.x = __ldg(gamma + q * 4 + 0) * (vals[q * 4 + 0] - mu) * inv + __ldg(beta + q * 4 + 0);
            o.y = __ldg(gamma + q * 4 + 1) * (vals[q * 4 + 1] - mu) * inv + __ldg(beta + q * 4 + 1);
            o.z = __ldg(gamma + q * 4 + 2) * (vals[q * 4 + 2] - mu) * inv + __ldg(beta + q * 4 + 2);
            o.w = __ldg(gamma + q * 4 + 3) * (vals[q * 4 + 3] - mu) * inv + __ldg(beta + q * 4 + 3);
            *reinterpret_cast<float4*>(out + base + q * 4) = o;
        }
    }
}

extern "C" void kernel_launch(void* const* d_in, const int* in_sizes, int n_in,
                              void* d_out, int out_size) {
    const float* x     = (const float*)d_in[0];
    const float* w     = (const float*)d_in[1];
    const float* gamma = (const float*)d_in[2];
    const float* beta  = (const float*)d_in[3];
    // d_in[4] = num_iter (unused by the reference body)
    float* out = (float*)d_out;

    prep_weight_kernel<<<(KKDIM * NNDIM + 255) / 256, 256>>>(w);

    dim3 grid(128, BB);  // 128 w-tiles (covers 2046, last tile partial) x 16 batches
    capsule_gemm_ln_kernel<<<grid, 256>>>(x, gamma, beta, out);
}

// round 3
// speedup vs baseline: 1.6874x; 1.6874x over previous
#include <cuda_runtime.h>
#include <cuda_bf16.h>
#include <cstdint>

// CapsuleConv = GEMM (rows=(b,w,a)=130944, K=(k,n,x)=384, cols=(m,d)=128) + fused LayerNorm.
// Tensor-core path via baseline-PTX mma.sync bf16 (HMMA), split precision:
//   D = Ah*Bh + Al*Bh + Ah*Bl   (fp32 accumulate)

#define BB    16
#define NIN   32
#define LLEN  2048
#define MMO   32
#define WOUTN 2046
#define KTOT  384

#define WTILE   32          // w per CTA (M = 128 rows)
#define RSTRIDE 144         // smem row stride bytes (64 bf16 data + 8 pad)
#define MAT_BYTES (128 * RSTRIDE)             // 18432 per matrix
#define STAGE_BYTES (4 * MAT_BYTES)           // Ah Al Bh Bl = 73728
#define SMEM_BYTES  (2 * STAGE_BYTES)         // 147456
#define SSTRIDE 132         // epilogue fp32 row stride (floats)

// ---- persistent scratch (__device__ globals; no allocs in kernel_launch) ----
__device__ __nv_bfloat16 g_xh[(size_t)BB * NIN * LLEN * 16];
__device__ __nv_bfloat16 g_xl[(size_t)BB * NIN * LLEN * 16];
__device__ __nv_bfloat16 g_Bh[128 * KTOT];   // [c=m*4+d][kk=(k*32+n)*4+x]
__device__ __nv_bfloat16 g_Bl[128 * KTOT];

// ======================= helpers =======================
__device__ __forceinline__ uint32_t smem_u32(const void* p) {
    uint32_t a;
    asm("{ .reg .u64 t; cvta.to.shared.u64 t, %1; cvt.u32.u64 %0, t; }" : "=r"(a) : "l"(p));
    return a;
}
__device__ __forceinline__ void cp8(uint32_t dst, const void* src) {
    asm volatile("cp.async.ca.shared.global [%0], [%1], 8;" :: "r"(dst), "l"(src));
}
__device__ __forceinline__ void cp16(uint32_t dst, const void* src) {
    asm volatile("cp.async.cg.shared.global [%0], [%1], 16;" :: "r"(dst), "l"(src));
}
__device__ __forceinline__ void cp_commit() {
    asm volatile("cp.async.commit_group;" ::: "memory");
}
__device__ __forceinline__ void ldsm4(uint32_t* r, uint32_t addr) {
    asm volatile("ldmatrix.sync.aligned.m8n8.x4.shared.b16 {%0,%1,%2,%3}, [%4];"
                 : "=r"(r[0]), "=r"(r[1]), "=r"(r[2]), "=r"(r[3]) : "r"(addr));
}
__device__ __forceinline__ void mma16816(float* d, const uint32_t* a,
                                         uint32_t b0, uint32_t b1) {
    asm volatile(
        "mma.sync.aligned.m16n8k16.row.col.f32.bf16.bf16.f32 "
        "{%0,%1,%2,%3}, {%4,%5,%6,%7}, {%8,%9}, {%0,%1,%2,%3};"
        : "+f"(d[0]), "+f"(d[1]), "+f"(d[2]), "+f"(d[3])
        : "r"(a[0]), "r"(a[1]), "r"(a[2]), "r"(a[3]), "r"(b0), "r"(b1));
}
__device__ __forceinline__ uint32_t pk(__nv_bfloat16 a, __nv_bfloat16 b) {
    __nv_bfloat162 t(a, b);
    return *reinterpret_cast<uint32_t*>(&t);
}

// ======================= prepass: split x into bf16 hi/lo =======================
__global__ __launch_bounds__(256)
void split_x(const float* __restrict__ x) {
    const size_t i = (size_t)blockIdx.x * 256 + threadIdx.x;   // float4 index
    const float4 v = reinterpret_cast<const float4*>(x)[i];
    const __nv_bfloat16 hx = __float2bfloat16_rn(v.x), hy = __float2bfloat16_rn(v.y),
                        hz = __float2bfloat16_rn(v.z), hw = __float2bfloat16_rn(v.w);
    reinterpret_cast<uint2*>(g_xh)[i] = make_uint2(pk(hx, hy), pk(hz, hw));
    reinterpret_cast<uint2*>(g_xl)[i] = make_uint2(
        pk(__float2bfloat16_rn(v.x - __bfloat162float(hx)),
           __float2bfloat16_rn(v.y - __bfloat162float(hy))),
        pk(__float2bfloat16_rn(v.z - __bfloat162float(hz)),
           __float2bfloat16_rn(v.w - __bfloat162float(hw))));
}

// ======================= prepass: rearrange + split weight =======================
__global__ __launch_bounds__(256)
void prep_b(const float* __restrict__ w) {
    int idx = blockIdx.x * 256 + threadIdx.x;
    if (idx >= 128 * KTOT) return;
    int c = idx / KTOT, kk = idx - c * KTOT;
    int x = kk & 3, kn = kk >> 2, n = kn & 31, k = kn >> 5;
    int m = c >> 2, d = c & 3;
    float val = w[(((k * NIN + n) * 4 + x) * 4 + d) * MMO + m] * (1.0f / 32.0f);
    __nv_bfloat16 h = __float2bfloat16_rn(val);
    g_Bh[idx] = h;
    g_Bl[idx] = __float2bfloat16_rn(val - __bfloat162float(h));
}

// ======================= main kernel =======================
__device__ __forceinline__ void issue_stage(
    uint32_t sAh, uint32_t sAl, uint32_t sBh, uint32_t sBl,
    const __nv_bfloat16* __restrict__ xh_b,
    const __nv_bfloat16* __restrict__ xl_b,
    int w0, int s, int tid)
{
    const int k = s >> 1, n0 = (s & 1) << 4, kk0 = s * 64;
    // A: 2048 8B transfers per matrix (h and l); F -> a, wl, nl ; coalesced 256B runs
#pragma unroll
    for (int j = 0; j < 8; ++j) {
        const int F  = tid + 256 * j;
        const int a  = F & 3;
        const int wl = (F >> 2) & 31;
        const int nl = F >> 7;
        int l = w0 + wl + k; if (l > LLEN - 1) l = LLEN - 1;   // rows w>=WOUT: garbage, never stored
        const size_t src = ((size_t)(n0 + nl) * LLEN + l) * 16 + a * 4;
        const uint32_t dst = (uint32_t)((wl * 4 + a) * RSTRIDE + nl * 8);
        cp8(sAh + dst, xh_b + src);
        cp8(sAl + dst, xl_b + src);
    }
    // B: 1024 16B transfers per matrix
#pragma unroll
    for (int j = 0; j < 4; ++j) {
        const int u = tid + 256 * j;
        const int c = u >> 3, seg = u & 7;
        const uint32_t dst = (uint32_t)(c * RSTRIDE + seg * 16);
        const int gi = c * KTOT + kk0 + seg * 8;
        cp16(sBh + dst, g_Bh + gi);
        cp16(sBl + dst, g_Bl + gi);
    }
}

__global__ __launch_bounds__(256, 1)
void caps_mma_kernel(const float* __restrict__ gamma,
                     const float* __restrict__ beta,
                     float* __restrict__ out) {
    extern __shared__ char dsm[];
    const uint32_t smem = smem_u32(dsm);

    const int tid = threadIdx.x;
    const int wid = tid >> 5, lid = tid & 31;
    const int b  = blockIdx.y;
    const int w0 = blockIdx.x * WTILE;

    const __nv_bfloat16* xh_b = g_xh + (size_t)b * NIN * LLEN * 16;
    const __nv_bfloat16* xl_b = g_xl + (size_t)b * NIN * LLEN * 16;

    // warp tile: rows wm*32 (of 128), cols wn*64 (of 128)
    const int wm = wid & 3;
    const int wn = wid >> 2;
    const uint32_t lane_off = (uint32_t)((lid & 15) * RSTRIDE + (lid >> 4) * 16);

    float d[2][8][4];
#pragma unroll
    for (int i = 0; i < 2; i++)
#pragma unroll
        for (int j = 0; j < 8; j++)
#pragma unroll
            for (int q = 0; q < 4; q++) d[i][j][q] = 0.0f;

    issue_stage(smem, smem + MAT_BYTES, smem + 2 * MAT_BYTES, smem + 3 * MAT_BYTES,
                xh_b, xl_b, w0, 0, tid);
    cp_commit();

    for (int s = 0; s < 6; ++s) {
        const uint32_t buf = smem + (uint32_t)(s & 1) * STAGE_BYTES;
        if (s < 5) {
            const uint32_t nb = smem + (uint32_t)((s + 1) & 1) * STAGE_BYTES;
            issue_stage(nb, nb + MAT_BYTES, nb + 2 * MAT_BYTES, nb + 3 * MAT_BYTES,
                        xh_b, xl_b, w0, s + 1, tid);
            cp_commit();
            asm volatile("cp.async.wait_group 1;" ::: "memory");
        } else {
            asm volatile("cp.async.wait_group 0;" ::: "memory");
        }
        __syncthreads();

        const uint32_t sAh = buf                 + (uint32_t)(wm * 32) * RSTRIDE + lane_off;
        const uint32_t sAl = buf +     MAT_BYTES + (uint32_t)(wm * 32) * RSTRIDE + lane_off;
        const uint32_t sBh = buf + 2 * MAT_BYTES + (uint32_t)(wn * 64) * RSTRIDE + lane_off;
        const uint32_t sBl = buf + 3 * MAT_BYTES + (uint32_t)(wn * 64) * RSTRIDE + lane_off;

#pragma unroll
        for (int ks = 0; ks < 4; ++ks) {
            const uint32_t kb = ks * 32;   // k16 = 32 bytes
            uint32_t Ah[2][4], Al[2][4], Bh[4][4], Bl[4][4];
#pragma unroll
            for (int mf = 0; mf < 2; ++mf) {
                ldsm4(Ah[mf], sAh + (uint32_t)(mf * 16) * RSTRIDE + kb);
                ldsm4(Al[mf], sAl + (uint32_t)(mf * 16) * RSTRIDE + kb);
            }
#pragma unroll
            for (int bg = 0; bg < 4; ++bg) {
                ldsm4(Bh[bg], sBh + (uint32_t)(bg * 16) * RSTRIDE + kb);
                ldsm4(Bl[bg], sBl + (uint32_t)(bg * 16) * RSTRIDE + kb);
            }
            // regs of x4 over 16 rows x 16 k: r0=(rows0-7,k0-7) r1=(rows8-15,k0-7)
            //                                 r2=(rows0-7,k8-15) r3=(rows8-15,k8-15)
            // n-group 0 of a B x4: {r0, r2}; n-group 1: {r1, r3}
#pragma unroll
            for (int mf = 0; mf < 2; ++mf)
#pragma unroll
                for (int bg = 0; bg < 4; ++bg) {
                    float* d0 = d[mf][bg * 2];
                    float* d1 = d[mf][bg * 2 + 1];
                    mma16816(d0, Ah[mf], Bh[bg][0], Bh[bg][2]);
                    mma16816(d1, Ah[mf], Bh[bg][1], Bh[bg][3]);
                    mma16816(d0, Al[mf], Bh[bg][0], Bh[bg][2]);
                    mma16816(d1, Al[mf], Bh[bg][1], Bh[bg][3]);
                    mma16816(d0, Ah[mf], Bl[bg][0], Bl[bg][2]);
                    mma16816(d1, Ah[mf], Bl[bg][1], Bl[bg][3]);
                }
        }
        __syncthreads();
    }

    // ---- epilogue: accum -> smem, fused LayerNorm over (a,d)=16 ----
    float* S = reinterpret_cast<float*>(dsm);   // [128][SSTRIDE]
    const int g = lid >> 2, t = lid & 3;
#pragma unroll
    for (int mf = 0; mf < 2; ++mf)
#pragma unroll
        for (int ng = 0; ng < 8; ++ng) {
            const int r = wm * 32 + mf * 16 + g;
            const int c = wn * 64 + ng * 8 + t * 2;
            S[r * SSTRIDE + c]           = d[mf][ng][0];
            S[r * SSTRIDE + c + 1]       = d[mf][ng][1];
            S[(r + 8) * SSTRIDE + c]     = d[mf][ng][2];
            S[(r + 8) * SSTRIDE + c + 1] = d[mf][ng][3];
        }
    __syncthreads();

    float gam[16], bet[16];
#pragma unroll
    for (int i = 0; i < 16; i++) { gam[i] = __ldg(gamma + i); bet[i] = __ldg(beta + i); }

    // 1024 LN groups (wl 0..31 x m 0..31), 4 per thread
#pragma unroll
    for (int gq = 0; gq < 4; ++gq) {
        const int G  = tid + gq * 256;
        const int wl = G >> 5;
        const int m  = G & 31;
        const int w  = w0 + wl;
        if (w >= WOUTN) continue;

        float vals[16];
#pragma unroll
        for (int a = 0; a < 4; a++) {
            const float4 v = *reinterpret_cast<const float4*>(
                S + (wl * 4 + a) * SSTRIDE + m * 4);
            vals[a * 4 + 0] = v.x; vals[a * 4 + 1] = v.y;
            vals[a * 4 + 2] = v.z; vals[a * 4 + 3] = v.w;
        }
        float mu = 0.0f;
#pragma unroll
        for (int i = 0; i < 16; i++) mu += vals[i];
        mu *= 0.0625f;
        float var = 0.0f;
#pragma unroll
        for (int i = 0; i < 16; i++) {
            const float dv = vals[i] - mu;
            var = fmaf(dv, dv, var);
        }
        var *= 0.0625f;
        const float inv = rsqrtf(var + 1e-5f);

        const size_t base = (((size_t)b * MMO + m) * WOUTN + w) * 16;
#pragma unroll
        for (int q = 0; q < 4; q++) {
            float4 o;
            o.x = fmaf((vals[q * 4 + 0] - mu) * inv, gam[q * 4 + 0], bet[q * 4 + 0]);
            o.y = fmaf((vals[q * 4 + 1] - mu) * inv, gam[q * 4 + 1], bet[q * 4 + 1]);
            o.z = fmaf((vals[q * 4 + 2] - mu) * inv, gam[q * 4 + 2], bet[q * 4 + 2]);
            o.w = fmaf((vals[q * 4 + 3] - mu) * inv, gam[q * 4 + 3], bet[q * 4 + 3]);
            *reinterpret_cast<float4*>(out + base + q * 4) = o;
        }
    }
}

extern "C" void kernel_launch(void* const* d_in, const int* in_sizes, int n_in,
                              void* d_out, int out_size) {
    const float* x     = (const float*)d_in[0];
    const float* w     = (const float*)d_in[1];
    const float* gamma = (const float*)d_in[2];
    const float* beta  = (const float*)d_in[3];
    float* out = (float*)d_out;

    // prepass: 16.78M elems as 4.19M float4
    split_x<<<16384, 256>>>(x);
    prep_b<<<(128 * KTOT + 255) / 256, 256>>>(w);

    cudaFuncSetAttribute(caps_mma_kernel,
                         cudaFuncAttributeMaxDynamicSharedMemorySize, SMEM_BYTES);
    dim3 grid(64, BB);   // 64 w-tiles x 16 batches
    caps_mma_kernel<<<grid, 256, SMEM_BYTES>>>(gamma, beta, out);
}

// round 4
// speedup vs baseline: 1.7234x; 1.0213x over previous
#include <cuda_runtime.h>
#include <cuda_bf16.h>
#include <cstdint>

// CapsuleConv = GEMM (rows=(b,w,a)=130944, K=(k,n,x)=384, cols=(m,d)=128) + fused LayerNorm.
// mma.sync bf16 split precision (D = Ah*Bh + Al*Bh + Ah*Bl), with k-shared A:
// A tile (136 rows x 128 (n,x)) loaded ONCE; 3 k-passes read it at row offset 4k.

#define BB    16
#define NIN   32
#define LLEN  2048
#define MMO   32
#define WOUTN 2046

#define WTILE   32          // w per CTA (M = 128 output rows)
#define ASTRIDE 272         // smem row stride bytes (128 bf16 = 256B + 16 pad)
#define A_ROWS  136         // (WTILE + 2) * 4
#define A_MAT   (A_ROWS * ASTRIDE)        // 36992
#define B_MAT   (128 * ASTRIDE)           // 34816
#define OFF_AH  0
#define OFF_AL  A_MAT
#define OFF_B   (2 * A_MAT)               // 73984
#define B_BUF   (2 * B_MAT)               // 69632 (Bh then Bl)
#define SMEM_BYTES (2 * A_MAT + 2 * B_BUF)  // 213248
#define SSTRIDE 132         // epilogue fp32 row stride (floats)

// ---- persistent scratch ----
// xT[b][l][a][n*4+x] hi/lo bf16
__device__ __nv_bfloat16 g_xh[(size_t)BB * LLEN * 4 * 128];
__device__ __nv_bfloat16 g_xl[(size_t)BB * LLEN * 4 * 128];
// B[k][c=m*4+d][n*4+x] hi/lo bf16
__device__ __nv_bfloat16 g_Bh[3 * 128 * 128];
__device__ __nv_bfloat16 g_Bl[3 * 128 * 128];

// ======================= helpers =======================
__device__ __forceinline__ uint32_t smem_u32(const void* p) {
    uint32_t a;
    asm("{ .reg .u64 t; cvta.to.shared.u64 t, %1; cvt.u32.u64 %0, t; }" : "=r"(a) : "l"(p));
    return a;
}
__device__ __forceinline__ void cp16(uint32_t dst, const void* src) {
    asm volatile("cp.async.cg.shared.global [%0], [%1], 16;" :: "r"(dst), "l"(src));
}
__device__ __forceinline__ void cp_commit() {
    asm volatile("cp.async.commit_group;" ::: "memory");
}
__device__ __forceinline__ void ldsm4(uint32_t* r, uint32_t addr) {
    asm volatile("ldmatrix.sync.aligned.m8n8.x4.shared.b16 {%0,%1,%2,%3}, [%4];"
                 : "=r"(r[0]), "=r"(r[1]), "=r"(r[2]), "=r"(r[3]) : "r"(addr));
}
__device__ __forceinline__ void mma16816(float* d, const uint32_t* a,
                                         uint32_t b0, uint32_t b1) {
    asm volatile(
        "mma.sync.aligned.m16n8k16.row.col.f32.bf16.bf16.f32 "
        "{%0,%1,%2,%3}, {%4,%5,%6,%7}, {%8,%9}, {%0,%1,%2,%3};"
        : "+f"(d[0]), "+f"(d[1]), "+f"(d[2]), "+f"(d[3])
        : "r"(a[0]), "r"(a[1]), "r"(a[2]), "r"(a[3]), "r"(b0), "r"(b1));
}
__device__ __forceinline__ uint32_t pk(__nv_bfloat16 a, __nv_bfloat16 b) {
    __nv_bfloat162 t(a, b);
    return *reinterpret_cast<uint32_t*>(&t);
}

// ======================= prepass: transpose + split x =======================
// one thread per (b,l,n): reads 16 floats x[b][n][l][:], writes 4 rows (a) of 4 bf16
// lanes = n -> 256B contiguous stores per warp per a.
__global__ __launch_bounds__(256)
void split_x(const float* __restrict__ x) {
    const size_t t = (size_t)blockIdx.x * 256 + threadIdx.x;   // 2^20 threads
    const int n = (int)(t & 31);
    const int l = (int)((t >> 5) & 2047);
    const int b = (int)(t >> 16);
    const float4* src = reinterpret_cast<const float4*>(
        x + (((size_t)(b * NIN + n)) * LLEN + l) * 16);
    const size_t dbase = ((size_t)b * 8192 + (size_t)l * 4) * 128 + n * 4;
#pragma unroll
    for (int a = 0; a < 4; ++a) {
        const float4 v = src[a];
        const __nv_bfloat16 hx = __float2bfloat16_rn(v.x), hy = __float2bfloat16_rn(v.y),
                            hz = __float2bfloat16_rn(v.z), hw = __float2bfloat16_rn(v.w);
        *reinterpret_cast<uint2*>(g_xh + dbase + (size_t)a * 128) =
            make_uint2(pk(hx, hy), pk(hz, hw));
        *reinterpret_cast<uint2*>(g_xl + dbase + (size_t)a * 128) = make_uint2(
            pk(__float2bfloat16_rn(v.x - __bfloat162float(hx)),
               __float2bfloat16_rn(v.y - __bfloat162float(hy))),
            pk(__float2bfloat16_rn(v.z - __bfloat162float(hz)),
               __float2bfloat16_rn(v.w - __bfloat162float(hw))));
    }
}

// ======================= prepass: rearrange + split weight =======================
__global__ __launch_bounds__(256)
void prep_b(const float* __restrict__ w) {
    const int idx = blockIdx.x * 256 + threadIdx.x;
    if (idx >= 3 * 128 * 128) return;
    const int col = idx & 127;       // n*4+x
    const int row = idx >> 7;
    const int c = row & 127;         // m*4+d
    const int k = row >> 7;
    const int n = col >> 2, xx = col & 3;
    const int m = c >> 2, d = c & 3;
    const float val = w[(((k * NIN + n) * 4 + xx) * 4 + d) * MMO + m] * (1.0f / 32.0f);
    const __nv_bfloat16 h = __float2bfloat16_rn(val);
    g_Bh[idx] = h;
    g_Bl[idx] = __float2bfloat16_rn(val - __bfloat162float(h));
}

// ======================= main kernel =======================
__global__ __launch_bounds__(256, 1)
void caps_mma_kernel(const float* __restrict__ gamma,
                     const float* __restrict__ beta,
                     float* __restrict__ out) {
    extern __shared__ char dsm[];
    const uint32_t smem = smem_u32(dsm);

    const int tid = threadIdx.x;
    const int wid = tid >> 5, lid = tid & 31;
    const int b  = blockIdx.y;
    const int w0 = blockIdx.x * WTILE;

    const int wm = wid & 3;           // row group: rows wm*32 .. +32
    const int wn = wid >> 2;          // col group: cols wn*64 .. +64
    const uint32_t lane_off = (uint32_t)((lid & 15) * ASTRIDE + (lid >> 4) * 16);

    const __nv_bfloat16* xh_b = g_xh + (size_t)b * 8192 * 128;
    const __nv_bfloat16* xl_b = g_xl + (size_t)b * 8192 * 128;

    // ---- issue A (hi+lo): 136 rows x 16 cp16 per matrix = 2176 each ----
#pragma unroll
    for (int j = 0; j < 9; ++j) {
        const int u = tid + 256 * j;
        if (u < A_ROWS * 16) {
            const int row = u >> 4, seg = u & 15;
            int l = w0 + (row >> 2);
            if (l > LLEN - 1) l = LLEN - 1;   // rows for w>=WOUT: garbage, never stored
            const size_t src = ((size_t)l * 4 + (row & 3)) * 128 + seg * 8;
            const uint32_t dst = (uint32_t)(row * ASTRIDE + seg * 16);
            cp16(smem + OFF_AH + dst, xh_b + src);
            cp16(smem + OFF_AL + dst, xl_b + src);
        }
    }
    // ---- issue B[0] into buf0, same commit group as A ----
#pragma unroll
    for (int j = 0; j < 8; ++j) {
        const int u = tid + 256 * j;
        const int row = u >> 4, seg = u & 15;
        const size_t src = (size_t)(0 * 128 + row) * 128 + seg * 8;
        const uint32_t dst = (uint32_t)(row * ASTRIDE + seg * 16);
        cp16(smem + OFF_B + dst, g_Bh + src);
        cp16(smem + OFF_B + B_MAT + dst, g_Bl + src);
    }
    cp_commit();   // group 0: A + B0

    // ---- issue B[1] into buf1 ----
#pragma unroll
    for (int j = 0; j < 8; ++j) {
        const int u = tid + 256 * j;
        const int row = u >> 4, seg = u & 15;
        const size_t src = (size_t)(1 * 128 + row) * 128 + seg * 8;
        const uint32_t dst = (uint32_t)(row * ASTRIDE + seg * 16);
        cp16(smem + OFF_B + B_BUF + dst, g_Bh + src);
        cp16(smem + OFF_B + B_BUF + B_MAT + dst, g_Bl + src);
    }
    cp_commit();   // group 1: B1

    float d[2][8][4];
#pragma unroll
    for (int i = 0; i < 2; i++)
#pragma unroll
        for (int j = 0; j < 8; j++)
#pragma unroll
            for (int q = 0; q < 4; q++) d[i][j][q] = 0.0f;

    for (int k = 0; k < 3; ++k) {
        if (k == 0) {
            asm volatile("cp.async.wait_group 1;" ::: "memory");   // A+B0 ready
        } else if (k == 1) {
            // buf0 free (all warps past k0): issue B2 into buf0
            __syncthreads();
#pragma unroll
            for (int j = 0; j < 8; ++j) {
                const int u = tid + 256 * j;
                const int row = u >> 4, seg = u & 15;
                const size_t src = (size_t)(2 * 128 + row) * 128 + seg * 8;
                const uint32_t dst = (uint32_t)(row * ASTRIDE + seg * 16);
                cp16(smem + OFF_B + dst, g_Bh + src);
                cp16(smem + OFF_B + B_MAT + dst, g_Bl + src);
            }
            cp_commit();   // group 2: B2
            asm volatile("cp.async.wait_group 1;" ::: "memory");   // B1 ready
        } else {
            asm volatile("cp.async.wait_group 0;" ::: "memory");   // B2 ready
        }
        __syncthreads();

        const uint32_t bufB = smem + OFF_B + (uint32_t)((k & 1) ? B_BUF : 0);
        const uint32_t sAh = smem + OFF_AH + (uint32_t)((wm * 32 + 4 * k) * ASTRIDE) + lane_off;
        const uint32_t sAl = smem + OFF_AL + (uint32_t)((wm * 32 + 4 * k) * ASTRIDE) + lane_off;
        const uint32_t sBh = bufB + (uint32_t)(wn * 64 * ASTRIDE) + lane_off;
        const uint32_t sBl = sBh + B_MAT;

#pragma unroll
        for (int ks = 0; ks < 8; ++ks) {
            const uint32_t kb = ks * 32;   // k16 step = 32 bytes
            uint32_t Ah[2][4], Al[2][4], Bh[4][4], Bl[4][4];
#pragma unroll
            for (int mf = 0; mf < 2; ++mf) {
                ldsm4(Ah[mf], sAh + (uint32_t)(mf * 16) * ASTRIDE + kb);
                ldsm4(Al[mf], sAl + (uint32_t)(mf * 16) * ASTRIDE + kb);
            }
#pragma unroll
            for (int bg = 0; bg < 4; ++bg) {
                ldsm4(Bh[bg], sBh + (uint32_t)(bg * 16) * ASTRIDE + kb);
                ldsm4(Bl[bg], sBl + (uint32_t)(bg * 16) * ASTRIDE + kb);
            }
#pragma unroll
            for (int mf = 0; mf < 2; ++mf)
#pragma unroll
                for (int bg = 0; bg < 4; ++bg) {
                    float* d0 = d[mf][bg * 2];
                    float* d1 = d[mf][bg * 2 + 1];
                    mma16816(d0, Ah[mf], Bh[bg][0], Bh[bg][2]);
                    mma16816(d1, Ah[mf], Bh[bg][1], Bh[bg][3]);
                    mma16816(d0, Al[mf], Bh[bg][0], Bh[bg][2]);
                    mma16816(d1, Al[mf], Bh[bg][1], Bh[bg][3]);
                    mma16816(d0, Ah[mf], Bl[bg][0], Bl[bg][2]);
                    mma16816(d1, Ah[mf], Bl[bg][1], Bl[bg][3]);
                }
        }
    }

    // ---- epilogue: accum -> smem, fused LayerNorm over (a,d)=16 ----
    __syncthreads();
    float* S = reinterpret_cast<float*>(dsm);   // [128][SSTRIDE]
    const int g = lid >> 2, t4 = lid & 3;
#pragma unroll
    for (int mf = 0; mf < 2; ++mf)
#pragma unroll
        for (int ng = 0; ng < 8; ++ng) {
            const int r = wm * 32 + mf * 16 + g;
            const int c = wn * 64 + ng * 8 + t4 * 2;
            S[r * SSTRIDE + c]           = d[mf][ng][0];
            S[r * SSTRIDE + c + 1]       = d[mf][ng][1];
            S[(r + 8) * SSTRIDE + c]     = d[mf][ng][2];
            S[(r + 8) * SSTRIDE + c + 1] = d[mf][ng][3];
        }
    __syncthreads();

    float gam[16], bet[16];
#pragma unroll
    for (int i = 0; i < 16; i++) { gam[i] = __ldg(gamma + i); bet[i] = __ldg(beta + i); }

#pragma unroll
    for (int gq = 0; gq < 4; ++gq) {
        const int G  = tid + gq * 256;
        const int wl = G >> 5;
        const int m  = G & 31;
        const int w  = w0 + wl;
        if (w >= WOUTN) continue;

        float vals[16];
#pragma unroll
        for (int a = 0; a < 4; a++) {
            const float4 v = *reinterpret_cast<const float4*>(
                S + (wl * 4 + a) * SSTRIDE + m * 4);
            vals[a * 4 + 0] = v.x; vals[a * 4 + 1] = v.y;
            vals[a * 4 + 2] = v.z; vals[a * 4 + 3] = v.w;
        }
        float mu = 0.0f;
#pragma unroll
        for (int i = 0; i < 16; i++) mu += vals[i];
        mu *= 0.0625f;
        float var = 0.0f;
#pragma unroll
        for (int i = 0; i < 16; i++) {
            const float dv = vals[i] - mu;
            var = fmaf(dv, dv, var);
        }
        var *= 0.0625f;
        const float inv = rsqrtf(var + 1e-5f);

        const size_t base = (((size_t)b * MMO + m) * WOUTN + w) * 16;
#pragma unroll
        for (int q = 0; q < 4; q++) {
            float4 o;
            o.x = fmaf((vals[q * 4 + 0] - mu) * inv, gam[q * 4 + 0], bet[q * 4 + 0]);
            o.y = fmaf((vals[q * 4 + 1] - mu) * inv, gam[q * 4 + 1], bet[q * 4 + 1]);
            o.z = fmaf((vals[q * 4 + 2] - mu) * inv, gam[q * 4 + 2], bet[q * 4 + 2]);
            o.w = fmaf((vals[q * 4 + 3] - mu) * inv, gam[q * 4 + 3], bet[q * 4 + 3]);
            *reinterpret_cast<float4*>(out + base + q * 4) = o;
        }
    }
}

extern "C" void kernel_launch(void* const* d_in, const int* in_sizes, int n_in,
                              void* d_out, int out_size) {
    const float* x     = (const float*)d_in[0];
    const float* w     = (const float*)d_in[1];
    const float* gamma = (const float*)d_in[2];
    const float* beta  = (const float*)d_in[3];
    float* out = (float*)d_out;

    split_x<<<4096, 256>>>(x);                          // 2^20 threads
    prep_b<<<(3 * 128 * 128 + 255) / 256, 256>>>(w);

    cudaFuncSetAttribute(caps_mma_kernel,
                         cudaFuncAttributeMaxDynamicSharedMemorySize, SMEM_BYTES);
    dim3 grid(64, BB);   // 64 w-tiles x 16 batches
    caps_mma_kernel<<<grid, 256, SMEM_BYTES>>>(gamma, beta, out);
}

// round 5
// speedup vs baseline: 2.2513x; 1.3063x over previous
#include <cuda_runtime.h>
#include <cuda_fp16.h>
#include <cstdint>

// CapsuleConv = GEMM (rows=(b,w,a)=130944, K=(k,n,x)=384, cols=(m,d)=128) + fused LayerNorm.
// mma.sync fp16 asymmetric split: A = fp16(x) single; B = fp16 hi + fp16 lo of (w*32).
//   D = A*Bh + A*Bl  (fp32 accum), epilogue scales by 1/1024 before LN.
// A tile (136 rows x 128) loaded ONCE per CTA; 3 k-passes read at row offset 4k.

#define BB    16
#define NIN   32
#define LLEN  2048
#define MMO   32
#define WOUTN 2046

#define WTILE   32          // w per CTA (M = 128 output rows)
#define ASTRIDE 272         // smem row stride bytes (128 fp16 = 256B + 16 pad)
#define A_ROWS  136         // (WTILE + 2) * 4
#define A_MAT   (A_ROWS * ASTRIDE)        // 36992
#define B_MAT   (128 * ASTRIDE)           // 34816
#define OFF_B   A_MAT
#define B_BUF   (2 * B_MAT)               // 69632 (Bh then Bl)
#define SMEM_BYTES (A_MAT + 2 * B_BUF)    // 176256
#define SSTRIDE 132         // epilogue fp32 row stride (floats)
#define OUT_SCALE (1.0f / 1024.0f)

// ---- persistent scratch ----
__device__ __half g_xh[(size_t)BB * LLEN * 4 * 128];   // xT[b][l][a][n*4+x]
__device__ __half g_Bh[3 * 128 * 128];                 // B[k][c=m*4+d][n*4+x] * 1024 hi
__device__ __half g_Bl[3 * 128 * 128];                 // lo

// ======================= helpers =======================
__device__ __forceinline__ uint32_t smem_u32(const void* p) {
    uint32_t a;
    asm("{ .reg .u64 t; cvta.to.shared.u64 t, %1; cvt.u32.u64 %0, t; }" : "=r"(a) : "l"(p));
    return a;
}
__device__ __forceinline__ void cp16(uint32_t dst, const void* src) {
    asm volatile("cp.async.cg.shared.global [%0], [%1], 16;" :: "r"(dst), "l"(src));
}
__device__ __forceinline__ void cp_commit() {
    asm volatile("cp.async.commit_group;" ::: "memory");
}
__device__ __forceinline__ void ldsm4(uint32_t* r, uint32_t addr) {
    asm volatile("ldmatrix.sync.aligned.m8n8.x4.shared.b16 {%0,%1,%2,%3}, [%4];"
                 : "=r"(r[0]), "=r"(r[1]), "=r"(r[2]), "=r"(r[3]) : "r"(addr));
}
__device__ __forceinline__ void mma16816(float* d, const uint32_t* a,
                                         uint32_t b0, uint32_t b1) {
    asm volatile(
        "mma.sync.aligned.m16n8k16.row.col.f32.f16.f16.f32 "
        "{%0,%1,%2,%3}, {%4,%5,%6,%7}, {%8,%9}, {%0,%1,%2,%3};"
        : "+f"(d[0]), "+f"(d[1]), "+f"(d[2]), "+f"(d[3])
        : "r"(a[0]), "r"(a[1]), "r"(a[2]), "r"(a[3]), "r"(b0), "r"(b1));
}
__device__ __forceinline__ uint32_t pkh(__half a, __half b) {
    __half2 t(a, b);
    return *reinterpret_cast<uint32_t*>(&t);
}

// ======================= merged prepass =======================
// blocks [0, 4096): transpose+convert x -> g_xh fp16
// blocks [4096, 4288): rearrange+split weight -> g_Bh/g_Bl
__global__ __launch_bounds__(256)
void prep_all(const float* __restrict__ x, const float* __restrict__ w) {
    if (blockIdx.x < 4096) {
        const size_t t = (size_t)blockIdx.x * 256 + threadIdx.x;   // 2^20 threads
        const int n = (int)(t & 31);
        const int l = (int)((t >> 5) & 2047);
        const int b = (int)(t >> 16);
        const float4* src = reinterpret_cast<const float4*>(
            x + (((size_t)(b * NIN + n)) * LLEN + l) * 16);
        const size_t dbase = ((size_t)b * 8192 + (size_t)l * 4) * 128 + n * 4;
#pragma unroll
        for (int a = 0; a < 4; ++a) {
            const float4 v = src[a];
            *reinterpret_cast<uint2*>(g_xh + dbase + (size_t)a * 128) =
                make_uint2(pkh(__float2half_rn(v.x), __float2half_rn(v.y)),
                           pkh(__float2half_rn(v.z), __float2half_rn(v.w)));
        }
    } else {
        const int idx = (blockIdx.x - 4096) * 256 + threadIdx.x;   // < 49152
        const int col = idx & 127;       // n*4+x
        const int row = idx >> 7;
        const int c = row & 127;         // m*4+d
        const int k = row >> 7;
        const int n = col >> 2, xx = col & 3;
        const int m = c >> 2, d = c & 3;
        // B_eff = w/32; stored scaled by 1024 -> w*32
        const float val = w[(((k * NIN + n) * 4 + xx) * 4 + d) * MMO + m] * 32.0f;
        const __half h = __float2half_rn(val);
        g_Bh[idx] = h;
        g_Bl[idx] = __float2half_rn(val - __half2float(h));
    }
}

// ======================= main kernel =======================
__global__ __launch_bounds__(256, 1)
void caps_mma_kernel(const float* __restrict__ gamma,
                     const float* __restrict__ beta,
                     float* __restrict__ out) {
    extern __shared__ char dsm[];
    const uint32_t smem = smem_u32(dsm);

    const int tid = threadIdx.x;
    const int wid = tid >> 5, lid = tid & 31;
    const int b  = blockIdx.y;
    const int w0 = blockIdx.x * WTILE;

    const int wm = wid & 3;           // rows wm*32 .. +32
    const int wn = wid >> 2;          // cols wn*64 .. +64
    const uint32_t lane_off = (uint32_t)((lid & 15) * ASTRIDE + (lid >> 4) * 16);

    const __half* xh_b = g_xh + (size_t)b * 8192 * 128;

    // ---- issue A: 136 rows x 16 cp16 = 2176 ----
#pragma unroll
    for (int j = 0; j < 9; ++j) {
        const int u = tid + 256 * j;
        if (u < A_ROWS * 16) {
            const int row = u >> 4, seg = u & 15;
            int l = w0 + (row >> 2);
            if (l > LLEN - 1) l = LLEN - 1;   // rows for w>=WOUT: garbage, never stored
            const size_t src = ((size_t)l * 4 + (row & 3)) * 128 + seg * 8;
            cp16(smem + (uint32_t)(row * ASTRIDE + seg * 16), xh_b + src);
        }
    }
    // ---- issue B[0] into buf0 (same commit group as A) ----
#pragma unroll
    for (int j = 0; j < 8; ++j) {
        const int u = tid + 256 * j;                    // < 2048
        const int row = u >> 4, seg = u & 15;
        const size_t src = (size_t)row * 128 + seg * 8; // k=0 slice
        const uint32_t dst = (uint32_t)(row * ASTRIDE + seg * 16);
        cp16(smem + OFF_B + dst, g_Bh + src);
        cp16(smem + OFF_B + B_MAT + dst, g_Bl + src);
    }
    cp_commit();   // group 0: A + B0

    // ---- issue B[1] into buf1 ----
#pragma unroll
    for (int j = 0; j < 8; ++j) {
        const int u = tid + 256 * j;
        const int row = u >> 4, seg = u & 15;
        const size_t src = (size_t)(128 + row) * 128 + seg * 8;
        const uint32_t dst = (uint32_t)(row * ASTRIDE + seg * 16);
        cp16(smem + OFF_B + B_BUF + dst, g_Bh + src);
        cp16(smem + OFF_B + B_BUF + B_MAT + dst, g_Bl + src);
    }
    cp_commit();   // group 1: B1

    float d[2][8][4];
#pragma unroll
    for (int i = 0; i < 2; i++)
#pragma unroll
        for (int j = 0; j < 8; j++)
#pragma unroll
            for (int q = 0; q < 4; q++) d[i][j][q] = 0.0f;

    for (int k = 0; k < 3; ++k) {
        if (k == 0) {
            asm volatile("cp.async.wait_group 1;" ::: "memory");   // A+B0 ready
        } else if (k == 1) {
            __syncthreads();   // buf0 free
#pragma unroll
            for (int j = 0; j < 8; ++j) {
                const int u = tid + 256 * j;
                const int row = u >> 4, seg = u & 15;
                const size_t src = (size_t)(256 + row) * 128 + seg * 8;
                const uint32_t dst = (uint32_t)(row * ASTRIDE + seg * 16);
                cp16(smem + OFF_B + dst, g_Bh + src);
                cp16(smem + OFF_B + B_MAT + dst, g_Bl + src);
            }
            cp_commit();   // group 2: B2
            asm volatile("cp.async.wait_group 1;" ::: "memory");   // B1 ready
        } else {
            asm volatile("cp.async.wait_group 0;" ::: "memory");   // B2 ready
        }
        __syncthreads();

        const uint32_t bufB = smem + OFF_B + (uint32_t)((k & 1) ? B_BUF : 0);
        const uint32_t sA  = smem + (uint32_t)((wm * 32 + 4 * k) * ASTRIDE) + lane_off;
        const uint32_t sBh = bufB + (uint32_t)(wn * 64 * ASTRIDE) + lane_off;
        const uint32_t sBl = sBh + B_MAT;

#pragma unroll
        for (int ks = 0; ks < 8; ++ks) {
            const uint32_t kb = ks * 32;   // k16 step = 32 bytes
            uint32_t Ar[2][4], Bh[4][4], Bl[4][4];
#pragma unroll
            for (int mf = 0; mf < 2; ++mf)
                ldsm4(Ar[mf], sA + (uint32_t)(mf * 16) * ASTRIDE + kb);
#pragma unroll
            for (int bg = 0; bg < 4; ++bg) {
                ldsm4(Bh[bg], sBh + (uint32_t)(bg * 16) * ASTRIDE + kb);
                ldsm4(Bl[bg], sBl + (uint32_t)(bg * 16) * ASTRIDE + kb);
            }
#pragma unroll
            for (int mf = 0; mf < 2; ++mf)
#pragma unroll
                for (int bg = 0; bg < 4; ++bg) {
                    float* d0 = d[mf][bg * 2];
                    float* d1 = d[mf][bg * 2 + 1];
                    mma16816(d0, Ar[mf], Bh[bg][0], Bh[bg][2]);
                    mma16816(d1, Ar[mf], Bh[bg][1], Bh[bg][3]);
                    mma16816(d0, Ar[mf], Bl[bg][0], Bl[bg][2]);
                    mma16816(d1, Ar[mf], Bl[bg][1], Bl[bg][3]);
                }
        }
    }

    // ---- epilogue: accum -> smem, scale 1/1024, fused LayerNorm over (a,d)=16 ----
    __syncthreads();
    float* S = reinterpret_cast<float*>(dsm);   // [128][SSTRIDE]
    const int g = lid >> 2, t4 = lid & 3;
#pragma unroll
    for (int mf = 0; mf < 2; ++mf)
#pragma unroll
        for (int ng = 0; ng < 8; ++ng) {
            const int r = wm * 32 + mf * 16 + g;
            const int c = wn * 64 + ng * 8 + t4 * 2;
            S[r * SSTRIDE + c]           = d[mf][ng][0];
            S[r * SSTRIDE + c + 1]       = d[mf][ng][1];
            S[(r + 8) * SSTRIDE + c]     = d[mf][ng][2];
            S[(r + 8) * SSTRIDE + c + 1] = d[mf][ng][3];
        }
    __syncthreads();

    float gam[16], bet[16];
#pragma unroll
    for (int i = 0; i < 16; i++) { gam[i] = __ldg(gamma + i); bet[i] = __ldg(beta + i); }

#pragma unroll
    for (int gq = 0; gq < 4; ++gq) {
        const int G  = tid + gq * 256;
        const int wl = G >> 5;
        const int m  = G & 31;
        const int w  = w0 + wl;
        if (w >= WOUTN) continue;

        float vals[16];
#pragma unroll
        for (int a = 0; a < 4; a++) {
            const float4 v = *reinterpret_cast<const float4*>(
                S + (wl * 4 + a) * SSTRIDE + m * 4);
            vals[a * 4 + 0] = v.x * OUT_SCALE; vals[a * 4 + 1] = v.y * OUT_SCALE;
            vals[a * 4 + 2] = v.z * OUT_SCALE; vals[a * 4 + 3] = v.w * OUT_SCALE;
        }
        float mu = 0.0f;
#pragma unroll
        for (int i = 0; i < 16; i++) mu += vals[i];
        mu *= 0.0625f;
        float var = 0.0f;
#pragma unroll
        for (int i = 0; i < 16; i++) {
            const float dv = vals[i] - mu;
            var = fmaf(dv, dv, var);
        }
        var *= 0.0625f;
        const float inv = rsqrtf(var + 1e-5f);

        const size_t base = (((size_t)b * MMO + m) * WOUTN + w) * 16;
#pragma unroll
        for (int q = 0; q < 4; q++) {
            float4 o;
            o.x = fmaf((vals[q * 4 + 0] - mu) * inv, gam[q * 4 + 0], bet[q * 4 + 0]);
            o.y = fmaf((vals[q * 4 + 1] - mu) * inv, gam[q * 4 + 1], bet[q * 4 + 1]);
            o.z = fmaf((vals[q * 4 + 2] - mu) * inv, gam[q * 4 + 2], bet[q * 4 + 2]);
            o.w = fmaf((vals[q * 4 + 3] - mu) * inv, gam[q * 4 + 3], bet[q * 4 + 3]);
            *reinterpret_cast<float4*>(out + base + q * 4) = o;
        }
    }
}

extern "C" void kernel_launch(void* const* d_in, const int* in_sizes, int n_in,
                              void* d_out, int out_size) {
    const float* x     = (const float*)d_in[0];
    const float* w     = (const float*)d_in[1];
    const float* gamma = (const float*)d_in[2];
    const float* beta  = (const float*)d_in[3];
    float* out = (float*)d_out;

    prep_all<<<4096 + 192, 256>>>(x, w);

    cudaFuncSetAttribute(caps_mma_kernel,
                         cudaFuncAttributeMaxDynamicSharedMemorySize, SMEM_BYTES);
    dim3 grid(64, BB);   // 64 w-tiles x 16 batches
    caps_mma_kernel<<<grid, 256, SMEM_BYTES>>>(gamma, beta, out);
}

// round 6
// speedup vs baseline: 3.3449x; 1.4858x over previous
#include <cuda_runtime.h>
#include <cuda_fp16.h>
#include <cstdint>

// CapsuleConv = GEMM (rows=(b,w,a)=130944, K=(k,n,x)=384, cols=(m,d)=128) + fused LayerNorm.
// Single-pass fp16 mma.sync: A = fp16(x), B = fp16(w)  (B_eff = w/32 via epilogue scale).
// A tile (136 rows x 128) loaded ONCE per CTA; 3 k-passes read it at row offset 4k.
// 2 CTAs/SM (smem 106.6KB, regs capped 128).

#define BB    16
#define NIN   32
#define LLEN  2048
#define MMO   32
#define WOUTN 2046

#define WTILE   32          // w per CTA (M = 128 output rows)
#define ASTRIDE 272         // smem row stride bytes (128 fp16 = 256B + 16 pad)
#define A_ROWS  136         // (WTILE + 2) * 4
#define A_MAT   (A_ROWS * ASTRIDE)        // 36992
#define B_MAT   (128 * ASTRIDE)           // 34816
#define OFF_B   A_MAT
#define SMEM_BYTES (A_MAT + 2 * B_MAT)    // 106624 -> 2 CTAs/SM
#define SSTRIDE 132         // epilogue fp32 row stride (floats)
#define OUT_SCALE (1.0f / 32.0f)

// ---- persistent scratch ----
__device__ __half g_xh[(size_t)BB * LLEN * 4 * 128];   // xT[b][l][a][n*4+x]
__device__ __half g_B [3 * 128 * 128];                 // B[k][c=m*4+d][n*4+x] = w (unscaled)

// ======================= helpers =======================
__device__ __forceinline__ uint32_t smem_u32(const void* p) {
    uint32_t a;
    asm("{ .reg .u64 t; cvta.to.shared.u64 t, %1; cvt.u32.u64 %0, t; }" : "=r"(a) : "l"(p));
    return a;
}
__device__ __forceinline__ void cp16(uint32_t dst, const void* src) {
    asm volatile("cp.async.cg.shared.global [%0], [%1], 16;" :: "r"(dst), "l"(src));
}
__device__ __forceinline__ void cp_commit() {
    asm volatile("cp.async.commit_group;" ::: "memory");
}
__device__ __forceinline__ void ldsm4(uint32_t* r, uint32_t addr) {
    asm volatile("ldmatrix.sync.aligned.m8n8.x4.shared.b16 {%0,%1,%2,%3}, [%4];"
                 : "=r"(r[0]), "=r"(r[1]), "=r"(r[2]), "=r"(r[3]) : "r"(addr));
}
__device__ __forceinline__ void mma16816(float* d, const uint32_t* a,
                                         uint32_t b0, uint32_t b1) {
    asm volatile(
        "mma.sync.aligned.m16n8k16.row.col.f32.f16.f16.f32 "
        "{%0,%1,%2,%3}, {%4,%5,%6,%7}, {%8,%9}, {%0,%1,%2,%3};"
        : "+f"(d[0]), "+f"(d[1]), "+f"(d[2]), "+f"(d[3])
        : "r"(a[0]), "r"(a[1]), "r"(a[2]), "r"(a[3]), "r"(b0), "r"(b1));
}
__device__ __forceinline__ uint32_t pkh(__half a, __half b) {
    __half2 t(a, b);
    return *reinterpret_cast<uint32_t*>(&t);
}

// ======================= merged prepass =======================
__global__ __launch_bounds__(256)
void prep_all(const float* __restrict__ x, const float* __restrict__ w) {
    if (blockIdx.x < 4096) {
        const size_t t = (size_t)blockIdx.x * 256 + threadIdx.x;   // 2^20 threads
        const int n = (int)(t & 31);
        const int l = (int)((t >> 5) & 2047);
        const int b = (int)(t >> 16);
        const float4* src = reinterpret_cast<const float4*>(
            x + (((size_t)(b * NIN + n)) * LLEN + l) * 16);
        const size_t dbase = ((size_t)b * 8192 + (size_t)l * 4) * 128 + n * 4;
#pragma unroll
        for (int a = 0; a < 4; ++a) {
            const float4 v = src[a];
            *reinterpret_cast<uint2*>(g_xh + dbase + (size_t)a * 128) =
                make_uint2(pkh(__float2half_rn(v.x), __float2half_rn(v.y)),
                           pkh(__float2half_rn(v.z), __float2half_rn(v.w)));
        }
    } else {
        const int idx = (blockIdx.x - 4096) * 256 + threadIdx.x;   // < 49152
        const int col = idx & 127;       // n*4+x
        const int row = idx >> 7;
        const int c = row & 127;         // m*4+d
        const int k = row >> 7;
        const int n = col >> 2, xx = col & 3;
        const int m = c >> 2, d = c & 3;
        g_B[idx] = __float2half_rn(w[(((k * NIN + n) * 4 + xx) * 4 + d) * MMO + m]);
    }
}

// ======================= main kernel =======================
__global__ __launch_bounds__(256, 2)
void caps_mma_kernel(const float* __restrict__ gamma,
                     const float* __restrict__ beta,
                     float* __restrict__ out) {
    extern __shared__ char dsm[];
    const uint32_t smem = smem_u32(dsm);

    const int tid = threadIdx.x;
    const int wid = tid >> 5, lid = tid & 31;
    const int b  = blockIdx.y;
    const int w0 = blockIdx.x * WTILE;

    const int wm = wid & 3;           // rows wm*32 .. +32
    const int wn = wid >> 2;          // cols wn*64 .. +64
    const uint32_t lane_off = (uint32_t)((lid & 15) * ASTRIDE + (lid >> 4) * 16);

    const __half* xh_b = g_xh + (size_t)b * 8192 * 128;

    // ---- issue A: 136 rows x 16 cp16 = 2176 ----
#pragma unroll
    for (int j = 0; j < 9; ++j) {
        const int u = tid + 256 * j;
        if (u < A_ROWS * 16) {
            const int row = u >> 4, seg = u & 15;
            int l = w0 + (row >> 2);
            if (l > LLEN - 1) l = LLEN - 1;   // rows for w>=WOUT: garbage, never stored
            const size_t src = ((size_t)l * 4 + (row & 3)) * 128 + seg * 8;
            cp16(smem + (uint32_t)(row * ASTRIDE + seg * 16), xh_b + src);
        }
    }
    // ---- issue B[0] into buf0 (same commit group as A) ----
#pragma unroll
    for (int j = 0; j < 8; ++j) {
        const int u = tid + 256 * j;                    // < 2048
        const int row = u >> 4, seg = u & 15;
        cp16(smem + OFF_B + (uint32_t)(row * ASTRIDE + seg * 16),
             g_B + (size_t)row * 128 + seg * 8);
    }
    cp_commit();   // group 0: A + B0

    // ---- issue B[1] into buf1 ----
#pragma unroll
    for (int j = 0; j < 8; ++j) {
        const int u = tid + 256 * j;
        const int row = u >> 4, seg = u & 15;
        cp16(smem + OFF_B + B_MAT + (uint32_t)(row * ASTRIDE + seg * 16),
             g_B + (size_t)(128 + row) * 128 + seg * 8);
    }
    cp_commit();   // group 1: B1

    float d[2][8][4];
#pragma unroll
    for (int i = 0; i < 2; i++)
#pragma unroll
        for (int j = 0; j < 8; j++)
#pragma unroll
            for (int q = 0; q < 4; q++) d[i][j][q] = 0.0f;

    for (int k = 0; k < 3; ++k) {
        if (k == 0) {
            asm volatile("cp.async.wait_group 1;" ::: "memory");   // A+B0 ready
        } else if (k == 1) {
            __syncthreads();   // buf0 free
#pragma unroll
            for (int j = 0; j < 8; ++j) {
                const int u = tid + 256 * j;
                const int row = u >> 4, seg = u & 15;
                cp16(smem + OFF_B + (uint32_t)(row * ASTRIDE + seg * 16),
                     g_B + (size_t)(256 + row) * 128 + seg * 8);
            }
            cp_commit();   // group 2: B2
            asm volatile("cp.async.wait_group 1;" ::: "memory");   // B1 ready
        } else {
            asm volatile("cp.async.wait_group 0;" ::: "memory");   // B2 ready
        }
        __syncthreads();

        const uint32_t sA = smem + (uint32_t)((wm * 32 + 4 * k) * ASTRIDE) + lane_off;
        const uint32_t sB = smem + OFF_B + (uint32_t)((k & 1) ? B_MAT : 0)
                          + (uint32_t)(wn * 64 * ASTRIDE) + lane_off;

#pragma unroll
        for (int ks = 0; ks < 8; ++ks) {
            const uint32_t kb = ks * 32;   // k16 step = 32 bytes
            uint32_t Ar[2][4], Br[4][4];
#pragma unroll
            for (int mf = 0; mf < 2; ++mf)
                ldsm4(Ar[mf], sA + (uint32_t)(mf * 16) * ASTRIDE + kb);
#pragma unroll
            for (int bg = 0; bg < 4; ++bg)
                ldsm4(Br[bg], sB + (uint32_t)(bg * 16) * ASTRIDE + kb);
#pragma unroll
            for (int mf = 0; mf < 2; ++mf)
#pragma unroll
                for (int bg = 0; bg < 4; ++bg) {
                    mma16816(d[mf][bg * 2],     Ar[mf], Br[bg][0], Br[bg][2]);
                    mma16816(d[mf][bg * 2 + 1], Ar[mf], Br[bg][1], Br[bg][3]);
                }
        }
    }

    // ---- epilogue: accum -> smem, scale 1/32, fused LayerNorm over (a,d)=16 ----
    __syncthreads();
    float* S = reinterpret_cast<float*>(dsm);   // [128][SSTRIDE]
    const int g = lid >> 2, t4 = lid & 3;
#pragma unroll
    for (int mf = 0; mf < 2; ++mf)
#pragma unroll
        for (int ng = 0; ng < 8; ++ng) {
            const int r = wm * 32 + mf * 16 + g;
            const int c = wn * 64 + ng * 8 + t4 * 2;
            S[r * SSTRIDE + c]           = d[mf][ng][0];
            S[r * SSTRIDE + c + 1]       = d[mf][ng][1];
            S[(r + 8) * SSTRIDE + c]     = d[mf][ng][2];
            S[(r + 8) * SSTRIDE + c + 1] = d[mf][ng][3];
        }
    __syncthreads();

    float gam[16], bet[16];
#pragma unroll
    for (int i = 0; i < 16; i++) { gam[i] = __ldg(gamma + i); bet[i] = __ldg(beta + i); }

#pragma unroll
    for (int gq = 0; gq < 4; ++gq) {
        const int G  = tid + gq * 256;
        const int wl = G >> 5;
        const int m  = G & 31;
        const int w  = w0 + wl;
        if (w >= WOUTN) continue;

        float vals[16];
#pragma unroll
        for (int a = 0; a < 4; a++) {
            const float4 v = *reinterpret_cast<const float4*>(
                S + (wl * 4 + a) * SSTRIDE + m * 4);
            vals[a * 4 + 0] = v.x * OUT_SCALE; vals[a * 4 + 1] = v.y * OUT_SCALE;
            vals[a * 4 + 2] = v.z * OUT_SCALE; vals[a * 4 + 3] = v.w * OUT_SCALE;
        }
        float mu = 0.0f;
#pragma unroll
        for (int i = 0; i < 16; i++) mu += vals[i];
        mu *= 0.0625f;
        float var = 0.0f;
#pragma unroll
        for (int i = 0; i < 16; i++) {
            const float dv = vals[i] - mu;
            var = fmaf(dv, dv, var);
        }
        var *= 0.0625f;
        const float inv = rsqrtf(var + 1e-5f);

        const size_t base = (((size_t)b * MMO + m) * WOUTN + w) * 16;
#pragma unroll
        for (int q = 0; q < 4; q++) {
            float4 o;
            o.x = fmaf((vals[q * 4 + 0] - mu) * inv, gam[q * 4 + 0], bet[q * 4 + 0]);
            o.y = fmaf((vals[q * 4 + 1] - mu) * inv, gam[q * 4 + 1], bet[q * 4 + 1]);
            o.z = fmaf((vals[q * 4 + 2] - mu) * inv, gam[q * 4 + 2], bet[q * 4 + 2]);
            o.w = fmaf((vals[q * 4 + 3] - mu) * inv, gam[q * 4 + 3], bet[q * 4 + 3]);
            *reinterpret_cast<float4*>(out + base + q * 4) = o;
        }
    }
}

extern "C" void kernel_launch(void* const* d_in, const int* in_sizes, int n_in,
                              void* d_out, int out_size) {
    const float* x     = (const float*)d_in[0];
    const float* w     = (const float*)d_in[1];
    const float* gamma = (const float*)d_in[2];
    const float* beta  = (const float*)d_in[3];
    float* out = (float*)d_out;

    prep_all<<<4096 + 192, 256>>>(x, w);

    cudaFuncSetAttribute(caps_mma_kernel,
                         cudaFuncAttributeMaxDynamicSharedMemorySize, SMEM_BYTES);
    dim3 grid(64, BB);   // 64 w-tiles x 16 batches
    caps_mma_kernel<<<grid, 256, SMEM_BYTES>>>(gamma, beta, out);
}

// round 7
// speedup vs baseline: 3.6976x; 1.1054x over previous
#include <cuda_runtime.h>
#include <cuda_fp16.h>
#include <cstdint>

// CapsuleConv = GEMM (rows=(b,w,a)=130944, K=(k,n,x)=384, cols=(m,d)=128) + fused LayerNorm.
// Single-pass fp16 mma.sync: A = fp16(x) converted INLINE from fp32, B = fp16(w).
// A tile (136 rows x 128) built once per CTA; 3 k-passes read it at row offset 4k.
// 2 CTAs/SM (smem 106.6KB, regs capped 128). Only prepass left: tiny B rearrange.

#define BB    16
#define NIN   32
#define LLEN  2048
#define MMO   32
#define WOUTN 2046

#define WTILE   32          // w per CTA (M = 128 output rows)
#define ASTRIDE 272         // smem row stride bytes (128 fp16 = 256B + 16 pad)
#define A_ROWS  136         // (WTILE + 2) * 4
#define A_MAT   (A_ROWS * ASTRIDE)        // 36992
#define B_MAT   (128 * ASTRIDE)           // 34816
#define OFF_B   A_MAT
#define SMEM_BYTES (A_MAT + 2 * B_MAT)    // 106624 -> 2 CTAs/SM
#define SSTRIDE 132         // epilogue fp32 row stride (floats)
#define OUT_SCALE (1.0f / 32.0f)

// ---- persistent scratch: rearranged fp16 weight only ----
__device__ __half g_B[3 * 128 * 128];     // B[k][c=m*4+d][n*4+x] = w (unscaled)

// ======================= helpers =======================
__device__ __forceinline__ uint32_t smem_u32(const void* p) {
    uint32_t a;
    asm("{ .reg .u64 t; cvta.to.shared.u64 t, %1; cvt.u32.u64 %0, t; }" : "=r"(a) : "l"(p));
    return a;
}
__device__ __forceinline__ void cp16(uint32_t dst, const void* src) {
    asm volatile("cp.async.cg.shared.global [%0], [%1], 16;" :: "r"(dst), "l"(src));
}
__device__ __forceinline__ void cp_commit() {
    asm volatile("cp.async.commit_group;" ::: "memory");
}
__device__ __forceinline__ void ldsm4(uint32_t* r, uint32_t addr) {
    asm volatile("ldmatrix.sync.aligned.m8n8.x4.shared.b16 {%0,%1,%2,%3}, [%4];"
                 : "=r"(r[0]), "=r"(r[1]), "=r"(r[2]), "=r"(r[3]) : "r"(addr));
}
__device__ __forceinline__ void mma16816(float* d, const uint32_t* a,
                                         uint32_t b0, uint32_t b1) {
    asm volatile(
        "mma.sync.aligned.m16n8k16.row.col.f32.f16.f16.f32 "
        "{%0,%1,%2,%3}, {%4,%5,%6,%7}, {%8,%9}, {%0,%1,%2,%3};"
        : "+f"(d[0]), "+f"(d[1]), "+f"(d[2]), "+f"(d[3])
        : "r"(a[0]), "r"(a[1]), "r"(a[2]), "r"(a[3]), "r"(b0), "r"(b1));
}
__device__ __forceinline__ uint32_t pkh(__half a, __half b) {
    __half2 t(a, b);
    return *reinterpret_cast<uint32_t*>(&t);
}

// ======================= tiny prepass: rearrange + convert weight =======================
__global__ __launch_bounds__(256)
void prep_b(const float* __restrict__ w) {
    const int idx = blockIdx.x * 256 + threadIdx.x;   // < 49152
    const int col = idx & 127;       // n*4+x
    const int row = idx >> 7;
    const int c = row & 127;         // m*4+d
    const int k = row >> 7;
    const int n = col >> 2, xx = col & 3;
    const int m = c >> 2, d = c & 3;
    g_B[idx] = __float2half_rn(w[(((k * NIN + n) * 4 + xx) * 4 + d) * MMO + m]);
}

// ======================= main kernel =======================
__global__ __launch_bounds__(256, 2)
void caps_mma_kernel(const float* __restrict__ x,
                     const float* __restrict__ gamma,
                     const float* __restrict__ beta,
                     float* __restrict__ out) {
    extern __shared__ char dsm[];
    const uint32_t smem = smem_u32(dsm);

    const int tid = threadIdx.x;
    const int wid = tid >> 5, lid = tid & 31;
    const int b  = blockIdx.y;
    const int w0 = blockIdx.x * WTILE;

    const int wm = wid & 3;           // rows wm*32 .. +32
    const int wn = wid >> 2;          // cols wn*64 .. +64
    const uint32_t lane_off = (uint32_t)((lid & 15) * ASTRIDE + (lid >> 4) * 16);

    const float* xb = x + (size_t)b * NIN * LLEN * 16;

    // ---- issue B[0] into buf0 ----
#pragma unroll
    for (int j = 0; j < 8; ++j) {
        const int u = tid + 256 * j;                    // < 2048
        const int row = u >> 4, seg = u & 15;
        cp16(smem + OFF_B + (uint32_t)(row * ASTRIDE + seg * 16),
             g_B + (size_t)row * 128 + seg * 8);
    }
    cp_commit();   // group 0: B0

    // ---- issue B[1] into buf1 ----
#pragma unroll
    for (int j = 0; j < 8; ++j) {
        const int u = tid + 256 * j;
        const int row = u >> 4, seg = u & 15;
        cp16(smem + OFF_B + B_MAT + (uint32_t)(row * ASTRIDE + seg * 16),
             g_B + (size_t)(128 + row) * 128 + seg * 8);
    }
    cp_commit();   // group 1: B1

    // ---- build A tile inline: LDG fp32 -> f2h -> STS (overlaps the cp.asyncs) ----
    // rows r = ll*4 + a (ll = l - w0), cols (n*4+xx); one float4 = one (n, l, a).
    // Part 1: ll in [0,32): l = w0+ll <= 2047, no clamp needed.
#pragma unroll
    for (int j = 0; j < 16; ++j) {
        const int F  = tid + 256 * j;     // < 4096
        const int a  = F & 3;
        const int ll = (F >> 2) & 31;
        const int nl = F >> 7;
        const float4 v = *reinterpret_cast<const float4*>(
            xb + ((size_t)nl * LLEN + (w0 + ll)) * 16 + a * 4);
        *reinterpret_cast<uint2*>(dsm + (uint32_t)((ll * 4 + a) * ASTRIDE + nl * 8)) =
            make_uint2(pkh(__float2half_rn(v.x), __float2half_rn(v.y)),
                       pkh(__float2half_rn(v.z), __float2half_rn(v.w)));
    }
    // Part 2: ll in {32, 33} (overhang rows; clamp; garbage only for w>=WOUT, never stored)
    {
        const int a  = tid & 3;
        const int ll = 32 + ((tid >> 2) & 1);
        const int nl = tid >> 3;
        int l = w0 + ll; if (l > LLEN - 1) l = LLEN - 1;
        const float4 v = *reinterpret_cast<const float4*>(
            xb + ((size_t)nl * LLEN + l) * 16 + a * 4);
        *reinterpret_cast<uint2*>(dsm + (uint32_t)((ll * 4 + a) * ASTRIDE + nl * 8)) =
            make_uint2(pkh(__float2half_rn(v.x), __float2half_rn(v.y)),
                       pkh(__float2half_rn(v.z), __float2half_rn(v.w)));
    }

    float d[2][8][4];
#pragma unroll
    for (int i = 0; i < 2; i++)
#pragma unroll
        for (int j = 0; j < 8; j++)
#pragma unroll
            for (int q = 0; q < 4; q++) d[i][j][q] = 0.0f;

    for (int k = 0; k < 3; ++k) {
        if (k == 0) {
            asm volatile("cp.async.wait_group 1;" ::: "memory");   // B0 ready
        } else if (k == 1) {
            __syncthreads();   // buf0 free
#pragma unroll
            for (int j = 0; j < 8; ++j) {
                const int u = tid + 256 * j;
                const int row = u >> 4, seg = u & 15;
                cp16(smem + OFF_B + (uint32_t)(row * ASTRIDE + seg * 16),
                     g_B + (size_t)(256 + row) * 128 + seg * 8);
            }
            cp_commit();   // group 2: B2
            asm volatile("cp.async.wait_group 1;" ::: "memory");   // B1 ready
        } else {
            asm volatile("cp.async.wait_group 0;" ::: "memory");   // B2 ready
        }
        __syncthreads();   // (k==0: also makes A STS visible)

        const uint32_t sA = smem + (uint32_t)((wm * 32 + 4 * k) * ASTRIDE) + lane_off;
        const uint32_t sB = smem + OFF_B + (uint32_t)((k & 1) ? B_MAT : 0)
                          + (uint32_t)(wn * 64 * ASTRIDE) + lane_off;

#pragma unroll
        for (int ks = 0; ks < 8; ++ks) {
            const uint32_t kb = ks * 32;   // k16 step = 32 bytes
            uint32_t Ar[2][4], Br[4][4];
#pragma unroll
            for (int mf = 0; mf < 2; ++mf)
                ldsm4(Ar[mf], sA + (uint32_t)(mf * 16) * ASTRIDE + kb);
#pragma unroll
            for (int bg = 0; bg < 4; ++bg)
                ldsm4(Br[bg], sB + (uint32_t)(bg * 16) * ASTRIDE + kb);
#pragma unroll
            for (int mf = 0; mf < 2; ++mf)
#pragma unroll
                for (int bg = 0; bg < 4; ++bg) {
                    mma16816(d[mf][bg * 2],     Ar[mf], Br[bg][0], Br[bg][2]);
                    mma16816(d[mf][bg * 2 + 1], Ar[mf], Br[bg][1], Br[bg][3]);
                }
        }
    }

    // ---- epilogue: accum -> smem, scale 1/32, fused LayerNorm over (a,d)=16 ----
    __syncthreads();
    float* S = reinterpret_cast<float*>(dsm);   // [128][SSTRIDE]
    const int g = lid >> 2, t4 = lid & 3;
#pragma unroll
    for (int mf = 0; mf < 2; ++mf)
#pragma unroll
        for (int ng = 0; ng < 8; ++ng) {
            const int r = wm * 32 + mf * 16 + g;
            const int c = wn * 64 + ng * 8 + t4 * 2;
            S[r * SSTRIDE + c]           = d[mf][ng][0];
            S[r * SSTRIDE + c + 1]       = d[mf][ng][1];
            S[(r + 8) * SSTRIDE + c]     = d[mf][ng][2];
            S[(r + 8) * SSTRIDE + c + 1] = d[mf][ng][3];
        }
    __syncthreads();

    float gam[16], bet[16];
#pragma unroll
    for (int i = 0; i < 16; i++) { gam[i] = __ldg(gamma + i); bet[i] = __ldg(beta + i); }

#pragma unroll
    for (int gq = 0; gq < 4; ++gq) {
        const int G  = tid + gq * 256;
        const int wl = G >> 5;
        const int m  = G & 31;
        const int w  = w0 + wl;
        if (w >= WOUTN) continue;

        float vals[16];
#pragma unroll
        for (int a = 0; a < 4; a++) {
            const float4 v = *reinterpret_cast<const float4*>(
                S + (wl * 4 + a) * SSTRIDE + m * 4);
            vals[a * 4 + 0] = v.x * OUT_SCALE; vals[a * 4 + 1] = v.y * OUT_SCALE;
            vals[a * 4 + 2] = v.z * OUT_SCALE; vals[a * 4 + 3] = v.w * OUT_SCALE;
        }
        float mu = 0.0f;
#pragma unroll
        for (int i = 0; i < 16; i++) mu += vals[i];
        mu *= 0.0625f;
        float var = 0.0f;
#pragma unroll
        for (int i = 0; i < 16; i++) {
            const float dv = vals[i] - mu;
            var = fmaf(dv, dv, var);
        }
        var *= 0.0625f;
        const float inv = rsqrtf(var + 1e-5f);

        const size_t base = (((size_t)b * MMO + m) * WOUTN + w) * 16;
#pragma unroll
        for (int q = 0; q < 4; q++) {
            float4 o;
            o.x = fmaf((vals[q * 4 + 0] - mu) * inv, gam[q * 4 + 0], bet[q * 4 + 0]);
            o.y = fmaf((vals[q * 4 + 1] - mu) * inv, gam[q * 4 + 1], bet[q * 4 + 1]);
            o.z = fmaf((vals[q * 4 + 2] - mu) * inv, gam[q * 4 + 2], bet[q * 4 + 2]);
            o.w = fmaf((vals[q * 4 + 3] - mu) * inv, gam[q * 4 + 3], bet[q * 4 + 3]);
            *reinterpret_cast<float4*>(out + base + q * 4) = o;
        }
    }
}

extern "C" void kernel_launch(void* const* d_in, const int* in_sizes, int n_in,
                              void* d_out, int out_size) {
    const float* x     = (const float*)d_in[0];
    const float* w     = (const float*)d_in[1];
    const float* gamma = (const float*)d_in[2];
    const float* beta  = (const float*)d_in[3];
    float* out = (float*)d_out;

    prep_b<<<192, 256>>>(w);

    cudaFuncSetAttribute(caps_mma_kernel,
                         cudaFuncAttributeMaxDynamicSharedMemorySize, SMEM_BYTES);
    dim3 grid(64, BB);   // 64 w-tiles x 16 batches
    caps_mma_kernel<<<grid, 256, SMEM_BYTES>>>(x, gamma, beta, out);
}